// round 15
// baseline (speedup 1.0000x reference)
#include <cuda_runtime.h>
#include <cuda_fp16.h>
#include <cstdint>

// Problem constants
#define NBATCH 2
#define LSEQ   2048
#define EMBD   1024
#define NHEAD  16
#define HDIM   64
#define MROWS  (NBATCH * LSEQ)   // 4096
#define QKV_ELEMS (NBATCH * NHEAD * LSEQ * HDIM)
#define W_ELEMS (EMBD * EMBD)
#define X_ELEMS (MROWS * EMBD)

// Scratch (device globals: no allocation allowed)
__device__ __half g_xh[X_ELEMS], g_xl[X_ELEMS];
__device__ __half g_wqh[W_ELEMS], g_wql[W_ELEMS];
__device__ __half g_wkh[W_ELEMS], g_wkl[W_ELEMS];
__device__ __half g_wvh[W_ELEMS];
__device__ __half g_woh[W_ELEMS];
__device__ __half g_qh[QKV_ELEMS], g_ql[QKV_ELEMS];
__device__ __half g_kh[QKV_ELEMS], g_kl[QKV_ELEMS];
__device__ __half g_vh[QKV_ELEMS];
__device__ __half g_oh[X_ELEMS];

__device__ __forceinline__ uint32_t smem_u32(const void* p) {
    uint32_t a;
    asm("{ .reg .u64 t; cvta.to.shared.u64 t, %1; cvt.u32.u64 %0, t; }"
        : "=r"(a) : "l"(p));
    return a;
}
__device__ __forceinline__ uint32_t packh2(float a, float b) {
    __half2 h = __floats2half2_rn(a, b);
    return *reinterpret_cast<uint32_t*>(&h);
}
__device__ __forceinline__ void cp_async16(uint32_t dst, const void* src) {
    asm volatile("cp.async.cg.shared.global [%0], [%1], 16;" :: "r"(dst), "l"(src));
}
#define CP_COMMIT() asm volatile("cp.async.commit_group;" ::: "memory")
#define CP_WAIT(N)  asm volatile("cp.async.wait_group %0;" :: "n"(N) : "memory")

#define LDSM_X4(r0, r1, r2, r3, addr) \
    asm volatile("ldmatrix.sync.aligned.m8n8.x4.shared.b16 {%0,%1,%2,%3}, [%4];" \
        : "=r"(r0), "=r"(r1), "=r"(r2), "=r"(r3) : "r"(addr))
#define LDSM_X4T(r0, r1, r2, r3, addr) \
    asm volatile("ldmatrix.sync.aligned.m8n8.x4.trans.shared.b16 {%0,%1,%2,%3}, [%4];" \
        : "=r"(r0), "=r"(r1), "=r"(r2), "=r"(r3) : "r"(addr))

__device__ __forceinline__ void mma_f16(float* c, const uint32_t* a, const uint32_t* b) {
    asm volatile(
        "mma.sync.aligned.m16n8k16.row.col.f32.f16.f16.f32 "
        "{%0,%1,%2,%3}, {%4,%5,%6,%7}, {%8,%9}, {%0,%1,%2,%3};"
        : "+f"(c[0]), "+f"(c[1]), "+f"(c[2]), "+f"(c[3])
        : "r"(a[0]), "r"(a[1]), "r"(a[2]), "r"(a[3]), "r"(b[0]), "r"(b[1]));
}

// ---------------- fused split pass ----------------
#define WN4 (W_ELEMS / 4)

__global__ void __launch_bounds__(256) split_all(
    const float4* __restrict__ x,  uint2* __restrict__ xh,  uint2* __restrict__ xl,
    const float4* __restrict__ wq, uint2* __restrict__ wqh, uint2* __restrict__ wql,
    const float4* __restrict__ wk, uint2* __restrict__ wkh, uint2* __restrict__ wkl,
    const float4* __restrict__ wv, uint2* __restrict__ wvh,
    const float4* __restrict__ wo, uint2* __restrict__ woh)
{
    const int y = blockIdx.y;
    const int i0 = blockIdx.x * 256 + threadIdx.x;

    auto split1 = [](float4 v, uint2& hi, uint2& lo) {
        __half h0 = __float2half_rn(v.x), h1 = __float2half_rn(v.y),
               h2 = __float2half_rn(v.z), h3 = __float2half_rn(v.w);
        __half2 p01 = __halves2half2(h0, h1), p23 = __halves2half2(h2, h3);
        hi = make_uint2(*(uint32_t*)&p01, *(uint32_t*)&p23);
        lo = make_uint2(packh2(v.x - __half2float(h0), v.y - __half2float(h1)),
                        packh2(v.z - __half2float(h2), v.w - __half2float(h3)));
    };

    if (y == 0) {
#pragma unroll
        for (int c = 0; c < 4; c++) {
            const int i = i0 + c * WN4;
            uint2 hi, lo;
            split1(x[i], hi, lo);
            xh[i] = hi; xl[i] = lo;
        }
    } else if (y == 1) {
        uint2 hi, lo; split1(wq[i0], hi, lo); wqh[i0] = hi; wql[i0] = lo;
    } else if (y == 2) {
        uint2 hi, lo; split1(wk[i0], hi, lo); wkh[i0] = hi; wkl[i0] = lo;
    } else if (y == 3) {
        float4 v = wv[i0];
        wvh[i0] = make_uint2(packh2(v.x, v.y), packh2(v.z, v.w));
    } else {
        float4 v = wo[i0];
        woh[i0] = make_uint2(packh2(v.x, v.y), packh2(v.z, v.w));
    }
}

// ---------------- GEMM: R14-proven (GSTR=40, 2-stage, X4 B-frag pairs) ----------
#define GSTR 40
#define GARR_B (128 * GSTR * 2)          // 10240 B
#define GEMM_SMEM 81920

template <int MODE, int NPROD>
__global__ void __launch_bounds__(256, 2) h16_gemm(
    const __half* __restrict__ Ah_g, const __half* __restrict__ Al_g,
    const __half* __restrict__ Bh_g, const __half* __restrict__ Bl_g,
    const float* __restrict__ gamma, const float* __restrict__ beta,
    const float* __restrict__ bias,
    __half* __restrict__ Ch, __half* __restrict__ Cl, float* __restrict__ C)
{
    constexpr uint32_t BOFF = (NPROD == 3 ? 2u : 1u) * GARR_B;
    constexpr uint32_t GSTG = (uint32_t)(NPROD + 1) * GARR_B;

    extern __shared__ char sm[];
    const uint32_t sbase = smem_u32(sm);
    const int tid  = threadIdx.x;
    const int lane = tid & 31;
    const int wid  = tid >> 5;
    const int warp_m = wid >> 2;
    const int warp_n = wid & 3;
    const int rb = blockIdx.x * 128;
    const int cb = blockIdx.y * 128;

    const int srow = tid >> 1;
    const int skoff = (tid & 1) * 16;
    const __half* Ap  = Ah_g + (size_t)(rb + srow) * EMBD + skoff;
    const __half* Alp = (NPROD == 3) ? Al_g + (size_t)(rb + srow) * EMBD + skoff : nullptr;
    const __half* Bp  = Bh_g + (size_t)(cb + srow) * EMBD + skoff;
    const __half* Blp = (NPROD >= 2) ? Bl_g + (size_t)(cb + srow) * EMBD + skoff : nullptr;
    const uint32_t sdst = ((uint32_t)srow * GSTR + (uint32_t)skoff) * 2;

    auto stage = [&](int s, int kc) {
        const uint32_t d = sbase + (uint32_t)s * GSTG + sdst;
        const int go = kc * 32;
        cp_async16(d,                 Ap + go);
        cp_async16(d + 16,            Ap + go + 8);
        if (NPROD == 3) {
            cp_async16(d + GARR_B,      Alp + go);
            cp_async16(d + GARR_B + 16, Alp + go + 8);
        }
        cp_async16(d + BOFF,      Bp + go);
        cp_async16(d + BOFF + 16, Bp + go + 8);
        if (NPROD >= 2) {
            cp_async16(d + BOFF + GARR_B,      Blp + go);
            cp_async16(d + BOFF + GARR_B + 16, Blp + go + 8);
        }
    };

    float acc[4][4][4] = {};

    const uint32_t aM = sbase
        + ((uint32_t)(warp_m * 64 + (lane & 15)) * GSTR + (uint32_t)((lane >> 4) << 3)) * 2;
    const uint32_t bN = sbase + BOFF
        + ((uint32_t)(warp_n * 32 + ((lane >> 4) << 3) + (lane & 7)) * GSTR
           + (uint32_t)(((lane & 15) >> 3) << 3)) * 2;

    auto compute = [&](int s) {
        const uint32_t so = (uint32_t)s * GSTG;
#pragma unroll
        for (int ks = 0; ks < 2; ks++) {
            uint32_t bh[4][2], bl[4][2];
#pragma unroll
            for (int nfp = 0; nfp < 2; nfp++) {
                const uint32_t ba = bN + so + (uint32_t)(nfp * (16 * GSTR * 2) + ks * 32);
                LDSM_X4(bh[2*nfp][0], bh[2*nfp][1], bh[2*nfp+1][0], bh[2*nfp+1][1], ba);
                if (NPROD >= 2) {
                    LDSM_X4(bl[2*nfp][0], bl[2*nfp][1], bl[2*nfp+1][0], bl[2*nfp+1][1],
                            ba + GARR_B);
                }
            }
#pragma unroll
            for (int mf = 0; mf < 4; mf++) {
                uint32_t ah[4], al[4];
                const uint32_t aa = aM + so + (uint32_t)(mf * (16 * GSTR * 2) + ks * 32);
                LDSM_X4(ah[0], ah[1], ah[2], ah[3], aa);
                if (NPROD == 3) { LDSM_X4(al[0], al[1], al[2], al[3], aa + GARR_B); }
#pragma unroll
                for (int nf = 0; nf < 4; nf++) {
                    mma_f16(acc[mf][nf], ah, bh[nf]);
                    if (NPROD >= 2) mma_f16(acc[mf][nf], ah, bl[nf]);
                    if (NPROD == 3) mma_f16(acc[mf][nf], al, bh[nf]);
                }
            }
        }
    };

    stage(0, 0);
    CP_COMMIT();
    const int NC = EMBD / 32;
    for (int kc = 0; kc < NC; kc++) {
        if (kc + 1 < NC) { stage((kc + 1) & 1, kc + 1); CP_COMMIT(); CP_WAIT(1); }
        else             { CP_WAIT(0); }
        __syncthreads();
        compute(kc & 1);
        __syncthreads();
    }

    const int g = lane >> 2;
    const int q = lane & 3;
    float* Ct = (float*)sm;   // [128][132]
#pragma unroll
    for (int mf = 0; mf < 4; mf++)
#pragma unroll
        for (int nf = 0; nf < 4; nf++) {
            const int r = warp_m * 64 + mf * 16 + g;
            const int c = warp_n * 32 + nf * 8 + q * 2;
            *(float2*)&Ct[r * 132 + c]       = make_float2(acc[mf][nf][0], acc[mf][nf][1]);
            *(float2*)&Ct[(r + 8) * 132 + c] = make_float2(acc[mf][nf][2], acc[mf][nf][3]);
        }
    __syncthreads();

    {
        const int row = tid >> 1;
        const int seg = tid & 1;
        const float* crow = &Ct[row * 132 + seg * 64];

        if (MODE == 2) {
            const int c0 = cb + seg * 64;
            float* dst = C + (size_t)(rb + row) * EMBD + c0;
#pragma unroll
            for (int j = 0; j < 16; j++) {
                float4 v = *(const float4*)&crow[4 * j];
                float4 b4 = *(const float4*)&bias[c0 + 4 * j];
                v.x += b4.x; v.y += b4.y; v.z += b4.z; v.w += b4.w;
                *(float4*)(dst + 4 * j) = v;
            }
        } else {
            float mean = 0.f, rstd = 0.f;
            if (MODE == 0) {
                float s = 0.f, s2 = 0.f;
#pragma unroll
                for (int j = 0; j < 16; j++) {
                    float4 v = *(const float4*)&crow[4 * j];
                    s  += v.x + v.y + v.z + v.w;
                    s2 += v.x * v.x + v.y * v.y + v.z * v.z + v.w * v.w;
                }
                mean = s * (1.0f / 64.0f);
                rstd = rsqrtf(s2 * (1.0f / 64.0f) - mean * mean + 1e-5f);
            }
            const int grow = rb + row;
            const int n = grow >> 11;
            const int l = grow & (LSEQ - 1);
            const int hd = (cb >> 6) + seg;
            const size_t off = ((size_t)((n * NHEAD + hd) * LSEQ + l)) * HDIM;
#pragma unroll
            for (int j = 0; j < 8; j++) {
                float v[8];
                *(float4*)&v[0] = *(const float4*)&crow[8 * j];
                *(float4*)&v[4] = *(const float4*)&crow[8 * j + 4];
                if (MODE == 0) {
#pragma unroll
                    for (int k2 = 0; k2 < 8; k2++)
                        v[k2] = (v[k2] - mean) * rstd * __ldg(gamma + 8 * j + k2)
                                + __ldg(beta + 8 * j + k2);
                }
                __half hh[8];
#pragma unroll
                for (int k2 = 0; k2 < 8; k2++) hh[k2] = __float2half_rn(v[k2]);
                *(uint4*)(Ch + off + 8 * j) = *(uint4*)hh;
                if (MODE == 0) {
                    __half ll[8];
#pragma unroll
                    for (int k2 = 0; k2 < 8; k2++)
                        ll[k2] = __float2half_rn(v[k2] - __half2float(hh[k2]));
                    *(uint4*)(Cl + off + 8 * j) = *(uint4*)ll;
                }
            }
        }
    }
}

// ---------------- Attention v7: S-pipelined across tiles, 4 buffers ----------------
#define APAD 72                          // 144B rows: 16B-aligned, conflict-free
#define KV_ARR_H (32 * APAD)
#define STAGE_B (3 * KV_ARR_H * 2)       // 13824 B (Kh|Kl|Vh)
#define NBUF 4
#define ATTN_SMEM (NBUF * STAGE_B)       // 55296 B

__global__ void __launch_bounds__(128, 3) attn_mma(
    const __half* __restrict__ Qh, const __half* __restrict__ Ql,
    const __half* __restrict__ Kh, const __half* __restrict__ Kl,
    const __half* __restrict__ Vh, __half* __restrict__ Oh)
{
    extern __shared__ __half smh[];
    const uint32_t sbase = smem_u32(smh);

    const int tid  = threadIdx.x;
    const int lane = tid & 31;
    const int wid  = tid >> 5;
    const int g    = lane >> 2;
    const int t    = lane & 3;
    const int nh   = blockIdx.y;
    const int qt   = gridDim.x - 1 - blockIdx.x;   // heavy tiles first
    const int qb   = qt * 64;
    const size_t base = (size_t)nh * LSEQ * HDIM;

    const int krow = tid >> 2;
    const int kcol = (tid & 3) * 16;
    const uint32_t kv_sm_off = ((uint32_t)krow * APAD + (uint32_t)kcol) * 2;

    auto stage_kv = [&](int b, int kt) {
        const size_t goff = base + (size_t)(kt * 32 + krow) * HDIM + kcol;
        const uint32_t s0 = sbase + (uint32_t)b * STAGE_B + kv_sm_off;
        cp_async16(s0,                        Kh + goff);
        cp_async16(s0 + 16,                   Kh + goff + 8);
        cp_async16(s0 + KV_ARR_H * 2,         Kl + goff);
        cp_async16(s0 + KV_ARR_H * 2 + 16,    Kl + goff + 8);
        cp_async16(s0 + KV_ARR_H * 4,         Vh + goff);
        cp_async16(s0 + KV_ARR_H * 4 + 16,    Vh + goff + 8);
    };

    // --- prologue: Q tile ---
    {
        const int qr = tid >> 1;
        const int qc = (tid & 1) * 32;
        const size_t goff = base + (size_t)(qb + qr) * HDIM + qc;
        const uint32_t s0 = sbase + ((uint32_t)qr * APAD + (uint32_t)qc) * 2;
#pragma unroll
        for (int i = 0; i < 4; i++) {
            cp_async16(s0 + i * 16,                 Qh + goff + i * 8);
            cp_async16(s0 + 64 * APAD * 2 + i * 16, Ql + goff + i * 8);
        }
        CP_COMMIT();
        CP_WAIT(0);
    }
    __syncthreads();

    uint32_t qfh[4][4], qfl[4][4];
    {
        const uint32_t qa = sbase
            + ((uint32_t)(wid * 16 + (lane & 15)) * APAD + (uint32_t)((lane >> 4) << 3)) * 2;
#pragma unroll
        for (int kc = 0; kc < 4; kc++) {
            LDSM_X4(qfh[kc][0], qfh[kc][1], qfh[kc][2], qfh[kc][3], qa + kc * 32);
            LDSM_X4(qfl[kc][0], qfl[kc][1], qfl[kc][2], qfl[kc][3],
                    qa + kc * 32 + 64 * APAD * 2);
        }
    }
    __syncthreads();   // Q reads complete before staging overwrites region

    const int nkt = 2 * (qt + 1);   // >= 2
    stage_kv(0, 0); CP_COMMIT();
    if (1 < nkt) { stage_kv(1, 1); CP_COMMIT(); }
    if (2 < nkt) { stage_kv(2, 2); CP_COMMIT(); }

    // fragment bases
    const uint32_t kO4 = sbase
        + ((uint32_t)(((lane >> 4) << 3) + (lane & 7)) * APAD
           + (uint32_t)(((lane & 15) >> 3) << 3)) * 2;
    const uint32_t vO4 = sbase + 4 * KV_ARR_H
        + ((uint32_t)(lane & 15) * APAD + (uint32_t)((lane >> 4) << 3)) * 2;

    // compute S for tile j into sc (incl. causal mask)
    auto compute_S = [&](float (&sc)[4][4], int j) {
        const uint32_t stg = (uint32_t)(j & (NBUF - 1)) * STAGE_B;
#pragma unroll
        for (int i4 = 0; i4 < 4; i4++)
#pragma unroll
            for (int j4 = 0; j4 < 4; j4++) sc[i4][j4] = 0.f;
#pragma unroll
        for (int kc = 0; kc < 4; kc++) {
#pragma unroll
            for (int nfp = 0; nfp < 2; nfp++) {
                const uint32_t ka = kO4 + stg + (uint32_t)(nfp * (16 * APAD * 2) + kc * 32);
                uint32_t bh[2][2], bl[2][2];
                LDSM_X4(bh[0][0], bh[0][1], bh[1][0], bh[1][1], ka);
                LDSM_X4(bl[0][0], bl[0][1], bl[1][0], bl[1][1], ka + KV_ARR_H * 2);
#pragma unroll
                for (int jj = 0; jj < 2; jj++) {
                    const int nf = 2 * nfp + jj;
                    mma_f16(sc[nf], qfh[kc], bh[jj]);
                    mma_f16(sc[nf], qfh[kc], bl[jj]);
                    mma_f16(sc[nf], qfl[kc], bh[jj]);
                }
            }
        }
        if (j >= 2 * qt) {
            const int diag = (j - 2 * qt) * 32;
            const int r0 = wid * 16 + g - diag;
            const int r1 = r0 + 8;
#pragma unroll
            for (int nf = 0; nf < 4; nf++) {
                const int c0 = nf * 8 + 2 * t;
                if (c0     > r0) sc[nf][0] = -1e30f;
                if (c0 + 1 > r0) sc[nf][1] = -1e30f;
                if (c0     > r1) sc[nf][2] = -1e30f;
                if (c0 + 1 > r1) sc[nf][3] = -1e30f;
            }
        }
    };

    float oc[8][4] = {};
    float m0 = -1e30f, m1 = -1e30f, l0 = 0.f, l1 = 0.f;
    float sc_cur[4][4], sc_nxt[4][4];

    // tile 0 visible, compute S(0)
    if (nkt > 2) { CP_WAIT(2); } else { CP_WAIT(1); }
    __syncthreads();
    compute_S(sc_cur, 0);

    for (int kt = 0; kt < nkt; kt++) {
        const bool have_next = (kt + 1 < nkt);
        if (have_next) {
            // make tile kt+1 visible (group for kt+2 may remain pending)
            if (kt + 2 < nkt) { CP_WAIT(1); } else { CP_WAIT(0); }
            __syncthreads();   // also retires buffer (kt+3)&3 (= tile kt-1) reads
            if (kt + 3 < nkt) {
                stage_kv((kt + 3) & (NBUF - 1), kt + 3);
                CP_COMMIT();
            }
            compute_S(sc_nxt, kt + 1);   // MMAs overlap the softmax/PV below
        }

        // ---- online softmax on sc_cur (deferred cross-thread l-sum) ----
        {
            float rm0 = -1e30f, rm1 = -1e30f;
#pragma unroll
            for (int nf = 0; nf < 4; nf++) {
                rm0 = fmaxf(rm0, fmaxf(sc_cur[nf][0], sc_cur[nf][1]));
                rm1 = fmaxf(rm1, fmaxf(sc_cur[nf][2], sc_cur[nf][3]));
            }
            rm0 = fmaxf(rm0, __shfl_xor_sync(0xffffffffu, rm0, 1));
            rm0 = fmaxf(rm0, __shfl_xor_sync(0xffffffffu, rm0, 2));
            rm1 = fmaxf(rm1, __shfl_xor_sync(0xffffffffu, rm1, 1));
            rm1 = fmaxf(rm1, __shfl_xor_sync(0xffffffffu, rm1, 2));

            const float mn0 = fmaxf(m0, rm0), mn1 = fmaxf(m1, rm1);
            const float cr0 = __expf(m0 - mn0), cr1 = __expf(m1 - mn1);
            float rs0 = 0.f, rs1 = 0.f;
#pragma unroll
            for (int nf = 0; nf < 4; nf++) {
                sc_cur[nf][0] = __expf(sc_cur[nf][0] - mn0);
                sc_cur[nf][1] = __expf(sc_cur[nf][1] - mn0);
                sc_cur[nf][2] = __expf(sc_cur[nf][2] - mn1);
                sc_cur[nf][3] = __expf(sc_cur[nf][3] - mn1);
                rs0 += sc_cur[nf][0] + sc_cur[nf][1];
                rs1 += sc_cur[nf][2] + sc_cur[nf][3];
            }
            l0 = l0 * cr0 + rs0;
            l1 = l1 * cr1 + rs1;
            m0 = mn0; m1 = mn1;
#pragma unroll
            for (int nf = 0; nf < 8; nf++) {
                oc[nf][0] *= cr0; oc[nf][1] *= cr0;
                oc[nf][2] *= cr1; oc[nf][3] *= cr1;
            }
        }

        // ---- O += P Vh for tile kt ----
        {
            const uint32_t stg = (uint32_t)(kt & (NBUF - 1)) * STAGE_B;
#pragma unroll
            for (int kc = 0; kc < 2; kc++) {
                uint32_t pah[4];
                {
                    const float* e0 = sc_cur[2 * kc];
                    const float* e1 = sc_cur[2 * kc + 1];
                    pah[0] = packh2(e0[0], e0[1]);
                    pah[1] = packh2(e0[2], e0[3]);
                    pah[2] = packh2(e1[0], e1[1]);
                    pah[3] = packh2(e1[2], e1[3]);
                }
#pragma unroll
                for (int nfp = 0; nfp < 4; nfp++) {
                    uint32_t vh[2][2];
                    LDSM_X4T(vh[0][0], vh[0][1], vh[1][0], vh[1][1],
                             vO4 + stg + (uint32_t)(kc * (16 * APAD * 2) + nfp * 32));
                    mma_f16(oc[2 * nfp],     pah, vh[0]);
                    mma_f16(oc[2 * nfp + 1], pah, vh[1]);
                }
            }
        }

        if (have_next) {
#pragma unroll
            for (int i4 = 0; i4 < 4; i4++)
#pragma unroll
                for (int j4 = 0; j4 < 4; j4++) sc_cur[i4][j4] = sc_nxt[i4][j4];
        }
    }

    // ---- epilogue: finish l reduction, normalize, fp16 scatter ----
    l0 += __shfl_xor_sync(0xffffffffu, l0, 1);
    l0 += __shfl_xor_sync(0xffffffffu, l0, 2);
    l1 += __shfl_xor_sync(0xffffffffu, l1, 1);
    l1 += __shfl_xor_sync(0xffffffffu, l1, 2);
    const float inv0 = 1.0f / l0, inv1 = 1.0f / l1;
    const int n = nh >> 4;
    const int h = nh & 15;
    const int r0 = qb + wid * 16 + g;
    const int r1 = r0 + 8;
#pragma unroll
    for (int nf = 0; nf < 8; nf++) {
        const int col = h * HDIM + nf * 8 + 2 * t;
        *(uint32_t*)(Oh + (size_t)(n * LSEQ + r0) * EMBD + col) =
            packh2(oc[nf][0] * inv0, oc[nf][1] * inv0);
        *(uint32_t*)(Oh + (size_t)(n * LSEQ + r1) * EMBD + col) =
            packh2(oc[nf][2] * inv1, oc[nf][3] * inv1);
    }
}

// ------------------------- launch -------------------------
extern "C" void kernel_launch(void* const* d_in, const int* in_sizes, int n_in,
                              void* d_out, int out_size)
{
    (void)in_sizes; (void)n_in; (void)out_size;
    const float* x  = (const float*)d_in[0];
    const float* Wq = (const float*)d_in[2];
    const float* Wk = (const float*)d_in[3];
    const float* Wv = (const float*)d_in[4];
    const float* gq = (const float*)d_in[5];
    const float* bq = (const float*)d_in[6];
    const float* gk = (const float*)d_in[7];
    const float* bk = (const float*)d_in[8];
    const float* Wo = (const float*)d_in[9];
    const float* bo = (const float*)d_in[10];
    float* out = (float*)d_out;

    __half *xh, *xl, *wqh, *wql, *wkh, *wkl, *wvh, *woh;
    __half *qh, *ql, *kh, *kl, *vh, *oh;
    cudaGetSymbolAddress((void**)&xh, g_xh);   cudaGetSymbolAddress((void**)&xl, g_xl);
    cudaGetSymbolAddress((void**)&wqh, g_wqh); cudaGetSymbolAddress((void**)&wql, g_wql);
    cudaGetSymbolAddress((void**)&wkh, g_wkh); cudaGetSymbolAddress((void**)&wkl, g_wkl);
    cudaGetSymbolAddress((void**)&wvh, g_wvh);
    cudaGetSymbolAddress((void**)&woh, g_woh);
    cudaGetSymbolAddress((void**)&qh, g_qh);   cudaGetSymbolAddress((void**)&ql, g_ql);
    cudaGetSymbolAddress((void**)&kh, g_kh);   cudaGetSymbolAddress((void**)&kl, g_kl);
    cudaGetSymbolAddress((void**)&vh, g_vh);
    cudaGetSymbolAddress((void**)&oh, g_oh);

    cudaFuncSetAttribute(h16_gemm<0,3>, cudaFuncAttributeMaxDynamicSharedMemorySize, GEMM_SMEM);
    cudaFuncSetAttribute(h16_gemm<1,1>, cudaFuncAttributeMaxDynamicSharedMemorySize, GEMM_SMEM);
    cudaFuncSetAttribute(h16_gemm<2,1>, cudaFuncAttributeMaxDynamicSharedMemorySize, GEMM_SMEM);
    cudaFuncSetAttribute(attn_mma, cudaFuncAttributeMaxDynamicSharedMemorySize, ATTN_SMEM);

    // #1: fused split
    split_all<<<dim3(WN4 / 256, 5), 256>>>(
        (const float4*)x,  (uint2*)xh,  (uint2*)xl,
        (const float4*)Wq, (uint2*)wqh, (uint2*)wql,
        (const float4*)Wk, (uint2*)wkh, (uint2*)wkl,
        (const float4*)Wv, (uint2*)wvh,
        (const float4*)Wo, (uint2*)woh);

    dim3 gg(MROWS / 128, EMBD / 128);
    // #2: V first (attn stays launch #5 for ncu)
    h16_gemm<1,1><<<gg, 256, GEMM_SMEM>>>(xh, nullptr, wvh, nullptr, nullptr, nullptr, nullptr,
                                          vh, nullptr, nullptr);
    // #3, #4: Q, K projections
    h16_gemm<0,3><<<gg, 256, GEMM_SMEM>>>(xh, xl, wqh, wql, gq, bq, nullptr, qh, ql, nullptr);
    h16_gemm<0,3><<<gg, 256, GEMM_SMEM>>>(xh, xl, wkh, wkl, gk, bk, nullptr, kh, kl, nullptr);

    // #5: attention
    attn_mma<<<dim3(LSEQ / 64, NBATCH * NHEAD), 128, ATTN_SMEM>>>(qh, ql, kh, kl, vh, oh);

    // #6: output projection
    h16_gemm<2,1><<<gg, 256, GEMM_SMEM>>>(oh, nullptr, woh, nullptr, nullptr, nullptr, bo,
                                          nullptr, nullptr, out);
}

// round 16
// speedup vs baseline: 1.0019x; 1.0019x over previous
#include <cuda_runtime.h>
#include <cuda_fp16.h>
#include <cstdint>

// Problem constants
#define NBATCH 2
#define LSEQ   2048
#define EMBD   1024
#define NHEAD  16
#define HDIM   64
#define MROWS  (NBATCH * LSEQ)   // 4096
#define QKV_ELEMS (NBATCH * NHEAD * LSEQ * HDIM)
#define W_ELEMS (EMBD * EMBD)
#define X_ELEMS (MROWS * EMBD)

// Scratch (device globals: no allocation allowed)
__device__ __half g_xh[X_ELEMS], g_xl[X_ELEMS];
__device__ __half g_wqh[W_ELEMS], g_wql[W_ELEMS];
__device__ __half g_wkh[W_ELEMS], g_wkl[W_ELEMS];
__device__ __half g_wvh[W_ELEMS];
__device__ __half g_woh[W_ELEMS];
__device__ __half g_qh[QKV_ELEMS], g_ql[QKV_ELEMS];
__device__ __half g_kh[QKV_ELEMS], g_kl[QKV_ELEMS];
__device__ __half g_vh[QKV_ELEMS];
__device__ __half g_oh[X_ELEMS];

__device__ __forceinline__ uint32_t smem_u32(const void* p) {
    uint32_t a;
    asm("{ .reg .u64 t; cvta.to.shared.u64 t, %1; cvt.u32.u64 %0, t; }"
        : "=r"(a) : "l"(p));
    return a;
}
__device__ __forceinline__ uint32_t packh2(float a, float b) {
    __half2 h = __floats2half2_rn(a, b);
    return *reinterpret_cast<uint32_t*>(&h);
}
__device__ __forceinline__ void cp_async16(uint32_t dst, const void* src) {
    asm volatile("cp.async.cg.shared.global [%0], [%1], 16;" :: "r"(dst), "l"(src));
}
#define CP_COMMIT() asm volatile("cp.async.commit_group;" ::: "memory")
#define CP_WAIT(N)  asm volatile("cp.async.wait_group %0;" :: "n"(N) : "memory")

#define LDSM_X4(r0, r1, r2, r3, addr) \
    asm volatile("ldmatrix.sync.aligned.m8n8.x4.shared.b16 {%0,%1,%2,%3}, [%4];" \
        : "=r"(r0), "=r"(r1), "=r"(r2), "=r"(r3) : "r"(addr))
#define LDSM_X4T(r0, r1, r2, r3, addr) \
    asm volatile("ldmatrix.sync.aligned.m8n8.x4.trans.shared.b16 {%0,%1,%2,%3}, [%4];" \
        : "=r"(r0), "=r"(r1), "=r"(r2), "=r"(r3) : "r"(addr))

__device__ __forceinline__ void mma_f16(float* c, const uint32_t* a, const uint32_t* b) {
    asm volatile(
        "mma.sync.aligned.m16n8k16.row.col.f32.f16.f16.f32 "
        "{%0,%1,%2,%3}, {%4,%5,%6,%7}, {%8,%9}, {%0,%1,%2,%3};"
        : "+f"(c[0]), "+f"(c[1]), "+f"(c[2]), "+f"(c[3])
        : "r"(a[0]), "r"(a[1]), "r"(a[2]), "r"(a[3]), "r"(b[0]), "r"(b[1]));
}

// ---------------- fused split pass ----------------
#define WN4 (W_ELEMS / 4)

__global__ void __launch_bounds__(256) split_all(
    const float4* __restrict__ x,  uint2* __restrict__ xh,  uint2* __restrict__ xl,
    const float4* __restrict__ wq, uint2* __restrict__ wqh, uint2* __restrict__ wql,
    const float4* __restrict__ wk, uint2* __restrict__ wkh, uint2* __restrict__ wkl,
    const float4* __restrict__ wv, uint2* __restrict__ wvh,
    const float4* __restrict__ wo, uint2* __restrict__ woh)
{
    const int y = blockIdx.y;
    const int i0 = blockIdx.x * 256 + threadIdx.x;

    auto split1 = [](float4 v, uint2& hi, uint2& lo) {
        __half h0 = __float2half_rn(v.x), h1 = __float2half_rn(v.y),
               h2 = __float2half_rn(v.z), h3 = __float2half_rn(v.w);
        __half2 p01 = __halves2half2(h0, h1), p23 = __halves2half2(h2, h3);
        hi = make_uint2(*(uint32_t*)&p01, *(uint32_t*)&p23);
        lo = make_uint2(packh2(v.x - __half2float(h0), v.y - __half2float(h1)),
                        packh2(v.z - __half2float(h2), v.w - __half2float(h3)));
    };

    if (y == 0) {
#pragma unroll
        for (int c = 0; c < 4; c++) {
            const int i = i0 + c * WN4;
            uint2 hi, lo;
            split1(x[i], hi, lo);
            xh[i] = hi; xl[i] = lo;
        }
    } else if (y == 1) {
        uint2 hi, lo; split1(wq[i0], hi, lo); wqh[i0] = hi; wql[i0] = lo;
    } else if (y == 2) {
        uint2 hi, lo; split1(wk[i0], hi, lo); wkh[i0] = hi; wkl[i0] = lo;
    } else if (y == 3) {
        float4 v = wv[i0];
        wvh[i0] = make_uint2(packh2(v.x, v.y), packh2(v.z, v.w));
    } else {
        float4 v = wo[i0];
        woh[i0] = make_uint2(packh2(v.x, v.y), packh2(v.z, v.w));
    }
}

// ---------------- GEMM: R14-proven (GSTR=40, 2-stage, X4 B-frag pairs) ----------
#define GSTR 40
#define GARR_B (128 * GSTR * 2)          // 10240 B
#define GEMM_SMEM 81920

template <int MODE, int NPROD>
__global__ void __launch_bounds__(256, 2) h16_gemm(
    const __half* __restrict__ Ah_g, const __half* __restrict__ Al_g,
    const __half* __restrict__ Bh_g, const __half* __restrict__ Bl_g,
    const float* __restrict__ gamma, const float* __restrict__ beta,
    const float* __restrict__ bias,
    __half* __restrict__ Ch, __half* __restrict__ Cl, float* __restrict__ C)
{
    constexpr uint32_t BOFF = (NPROD == 3 ? 2u : 1u) * GARR_B;
    constexpr uint32_t GSTG = (uint32_t)(NPROD + 1) * GARR_B;

    extern __shared__ char sm[];
    const uint32_t sbase = smem_u32(sm);
    const int tid  = threadIdx.x;
    const int lane = tid & 31;
    const int wid  = tid >> 5;
    const int warp_m = wid >> 2;
    const int warp_n = wid & 3;
    const int rb = blockIdx.x * 128;
    const int cb = blockIdx.y * 128;

    const int srow = tid >> 1;
    const int skoff = (tid & 1) * 16;
    const __half* Ap  = Ah_g + (size_t)(rb + srow) * EMBD + skoff;
    const __half* Alp = (NPROD == 3) ? Al_g + (size_t)(rb + srow) * EMBD + skoff : nullptr;
    const __half* Bp  = Bh_g + (size_t)(cb + srow) * EMBD + skoff;
    const __half* Blp = (NPROD >= 2) ? Bl_g + (size_t)(cb + srow) * EMBD + skoff : nullptr;
    const uint32_t sdst = ((uint32_t)srow * GSTR + (uint32_t)skoff) * 2;

    auto stage = [&](int s, int kc) {
        const uint32_t d = sbase + (uint32_t)s * GSTG + sdst;
        const int go = kc * 32;
        cp_async16(d,                 Ap + go);
        cp_async16(d + 16,            Ap + go + 8);
        if (NPROD == 3) {
            cp_async16(d + GARR_B,      Alp + go);
            cp_async16(d + GARR_B + 16, Alp + go + 8);
        }
        cp_async16(d + BOFF,      Bp + go);
        cp_async16(d + BOFF + 16, Bp + go + 8);
        if (NPROD >= 2) {
            cp_async16(d + BOFF + GARR_B,      Blp + go);
            cp_async16(d + BOFF + GARR_B + 16, Blp + go + 8);
        }
    };

    float acc[4][4][4] = {};

    const uint32_t aM = sbase
        + ((uint32_t)(warp_m * 64 + (lane & 15)) * GSTR + (uint32_t)((lane >> 4) << 3)) * 2;
    const uint32_t bN = sbase + BOFF
        + ((uint32_t)(warp_n * 32 + ((lane >> 4) << 3) + (lane & 7)) * GSTR
           + (uint32_t)(((lane & 15) >> 3) << 3)) * 2;

    auto compute = [&](int s) {
        const uint32_t so = (uint32_t)s * GSTG;
#pragma unroll
        for (int ks = 0; ks < 2; ks++) {
            uint32_t bh[4][2], bl[4][2];
#pragma unroll
            for (int nfp = 0; nfp < 2; nfp++) {
                const uint32_t ba = bN + so + (uint32_t)(nfp * (16 * GSTR * 2) + ks * 32);
                LDSM_X4(bh[2*nfp][0], bh[2*nfp][1], bh[2*nfp+1][0], bh[2*nfp+1][1], ba);
                if (NPROD >= 2) {
                    LDSM_X4(bl[2*nfp][0], bl[2*nfp][1], bl[2*nfp+1][0], bl[2*nfp+1][1],
                            ba + GARR_B);
                }
            }
#pragma unroll
            for (int mf = 0; mf < 4; mf++) {
                uint32_t ah[4], al[4];
                const uint32_t aa = aM + so + (uint32_t)(mf * (16 * GSTR * 2) + ks * 32);
                LDSM_X4(ah[0], ah[1], ah[2], ah[3], aa);
                if (NPROD == 3) { LDSM_X4(al[0], al[1], al[2], al[3], aa + GARR_B); }
#pragma unroll
                for (int nf = 0; nf < 4; nf++) {
                    mma_f16(acc[mf][nf], ah, bh[nf]);
                    if (NPROD >= 2) mma_f16(acc[mf][nf], ah, bl[nf]);
                    if (NPROD == 3) mma_f16(acc[mf][nf], al, bh[nf]);
                }
            }
        }
    };

    stage(0, 0);
    CP_COMMIT();
    const int NC = EMBD / 32;
    for (int kc = 0; kc < NC; kc++) {
        if (kc + 1 < NC) { stage((kc + 1) & 1, kc + 1); CP_COMMIT(); CP_WAIT(1); }
        else             { CP_WAIT(0); }
        __syncthreads();
        compute(kc & 1);
        __syncthreads();
    }

    const int g = lane >> 2;
    const int q = lane & 3;
    float* Ct = (float*)sm;   // [128][132]
#pragma unroll
    for (int mf = 0; mf < 4; mf++)
#pragma unroll
        for (int nf = 0; nf < 4; nf++) {
            const int r = warp_m * 64 + mf * 16 + g;
            const int c = warp_n * 32 + nf * 8 + q * 2;
            *(float2*)&Ct[r * 132 + c]       = make_float2(acc[mf][nf][0], acc[mf][nf][1]);
            *(float2*)&Ct[(r + 8) * 132 + c] = make_float2(acc[mf][nf][2], acc[mf][nf][3]);
        }
    __syncthreads();

    {
        const int row = tid >> 1;
        const int seg = tid & 1;
        const float* crow = &Ct[row * 132 + seg * 64];

        if (MODE == 2) {
            const int c0 = cb + seg * 64;
            float* dst = C + (size_t)(rb + row) * EMBD + c0;
#pragma unroll
            for (int j = 0; j < 16; j++) {
                float4 v = *(const float4*)&crow[4 * j];
                float4 b4 = *(const float4*)&bias[c0 + 4 * j];
                v.x += b4.x; v.y += b4.y; v.z += b4.z; v.w += b4.w;
                *(float4*)(dst + 4 * j) = v;
            }
        } else {
            float mean = 0.f, rstd = 0.f;
            if (MODE == 0) {
                float s = 0.f, s2 = 0.f;
#pragma unroll
                for (int j = 0; j < 16; j++) {
                    float4 v = *(const float4*)&crow[4 * j];
                    s  += v.x + v.y + v.z + v.w;
                    s2 += v.x * v.x + v.y * v.y + v.z * v.z + v.w * v.w;
                }
                mean = s * (1.0f / 64.0f);
                rstd = rsqrtf(s2 * (1.0f / 64.0f) - mean * mean + 1e-5f);
            }
            const int grow = rb + row;
            const int n = grow >> 11;
            const int l = grow & (LSEQ - 1);
            const int hd = (cb >> 6) + seg;
            const size_t off = ((size_t)((n * NHEAD + hd) * LSEQ + l)) * HDIM;
#pragma unroll
            for (int j = 0; j < 8; j++) {
                float v[8];
                *(float4*)&v[0] = *(const float4*)&crow[8 * j];
                *(float4*)&v[4] = *(const float4*)&crow[8 * j + 4];
                if (MODE == 0) {
#pragma unroll
                    for (int k2 = 0; k2 < 8; k2++)
                        v[k2] = (v[k2] - mean) * rstd * __ldg(gamma + 8 * j + k2)
                                + __ldg(beta + 8 * j + k2);
                }
                __half hh[8];
#pragma unroll
                for (int k2 = 0; k2 < 8; k2++) hh[k2] = __float2half_rn(v[k2]);
                *(uint4*)(Ch + off + 8 * j) = *(uint4*)hh;
                if (MODE == 0) {
                    __half ll[8];
#pragma unroll
                    for (int k2 = 0; k2 < 8; k2++)
                        ll[k2] = __float2half_rn(v[k2] - __half2float(hh[k2]));
                    *(uint4*)(Cl + off + 8 * j) = *(uint4*)ll;
                }
            }
        }
    }
}

// ---------------- Attention v8: 128-q tiles, 8 warps, 3-stage (R14 pipeline) -------
#define APAD 72                          // 144B rows: 16B-aligned, conflict-free
#define KV_ARR_H (32 * APAD)
#define STAGE_B (3 * KV_ARR_H * 2)       // 13824 B (Kh|Kl|Vh)
#define ATTN_SMEM (3 * STAGE_B)          // 41472 B  (Q prologue: 36864 B fits)
#define QROWS 128

__global__ void __launch_bounds__(256, 2) attn_mma(
    const __half* __restrict__ Qh, const __half* __restrict__ Ql,
    const __half* __restrict__ Kh, const __half* __restrict__ Kl,
    const __half* __restrict__ Vh, __half* __restrict__ Oh)
{
    extern __shared__ __half smh[];
    const uint32_t sbase = smem_u32(smh);

    const int tid  = threadIdx.x;
    const int lane = tid & 31;
    const int wid  = tid >> 5;      // 0..7
    const int g    = lane >> 2;
    const int t    = lane & 3;
    const int nh   = blockIdx.y;
    const int qt   = gridDim.x - 1 - blockIdx.x;   // heavy tiles first
    const int qb   = qt * QROWS;
    const size_t base = (size_t)nh * LSEQ * HDIM;

    // K/V staging: 32 rows x 64 halves, 256 threads -> 1 cp.async16 per array
    const int krow = tid >> 3;            // 0..31
    const int kcol = (tid & 7) * 8;       // 0..56
    const uint32_t kv_sm_off = ((uint32_t)krow * APAD + (uint32_t)kcol) * 2;

    auto stage_kv = [&](int b, int kt) {
        const size_t goff = base + (size_t)(kt * 32 + krow) * HDIM + kcol;
        const uint32_t s0 = sbase + (uint32_t)b * STAGE_B + kv_sm_off;
        cp_async16(s0,                Kh + goff);
        cp_async16(s0 + KV_ARR_H * 2, Kl + goff);
        cp_async16(s0 + KV_ARR_H * 4, Vh + goff);
    };

    // --- prologue: Q tile (128 x 64, hi+lo) staged into smem start ---
    {
        const int qr = tid >> 1;            // 0..127
        const int qc = (tid & 1) * 32;
        const size_t goff = base + (size_t)(qb + qr) * HDIM + qc;
        const uint32_t s0 = sbase + ((uint32_t)qr * APAD + (uint32_t)qc) * 2;
#pragma unroll
        for (int i = 0; i < 4; i++) {
            cp_async16(s0 + i * 16,                    Qh + goff + i * 8);
            cp_async16(s0 + QROWS * APAD * 2 + i * 16, Ql + goff + i * 8);
        }
        CP_COMMIT();
        CP_WAIT(0);
    }
    __syncthreads();

    uint32_t qfh[4][4], qfl[4][4];
    {
        const uint32_t qa = sbase
            + ((uint32_t)(wid * 16 + (lane & 15)) * APAD + (uint32_t)((lane >> 4) << 3)) * 2;
#pragma unroll
        for (int kc = 0; kc < 4; kc++) {
            LDSM_X4(qfh[kc][0], qfh[kc][1], qfh[kc][2], qfh[kc][3], qa + kc * 32);
            LDSM_X4(qfl[kc][0], qfl[kc][1], qfl[kc][2], qfl[kc][3],
                    qa + kc * 32 + QROWS * APAD * 2);
        }
    }
    __syncthreads();   // Q reads complete before K/V staging overwrites region

    const int nkt = 4 * (qt + 1);   // 32k tiles covering [0, qb+128)
    stage_kv(0, 0); CP_COMMIT();
    stage_kv(1, 1); CP_COMMIT();

    float oc[8][4] = {};
    float m0 = -1e30f, m1 = -1e30f, l0 = 0.f, l1 = 0.f;

    const uint32_t kO4 = sbase
        + ((uint32_t)(((lane >> 4) << 3) + (lane & 7)) * APAD
           + (uint32_t)(((lane & 15) >> 3) << 3)) * 2;
    const uint32_t vO4 = sbase + 4 * KV_ARR_H
        + ((uint32_t)(lane & 15) * APAD + (uint32_t)((lane >> 4) << 3)) * 2;

    int buf = 0;
    for (int kt = 0; kt < nkt; kt++) {
        if (kt + 1 < nkt) { CP_WAIT(1); } else { CP_WAIT(0); }
        __syncthreads();   // tile kt visible; buffer (buf+2)%3 retired
        if (kt + 2 < nkt) {
            int b2 = buf + 2; if (b2 >= 3) b2 -= 3;
            stage_kv(b2, kt + 2);
            CP_COMMIT();
        }

        const uint32_t stg = (uint32_t)buf * STAGE_B;

        // ---- S = Q K^T (3-product split), K frags via X4 pairs ----
        float sc[4][4] = {};
#pragma unroll
        for (int kc = 0; kc < 4; kc++) {
#pragma unroll
            for (int nfp = 0; nfp < 2; nfp++) {
                const uint32_t ka = kO4 + stg + (uint32_t)(nfp * (16 * APAD * 2) + kc * 32);
                uint32_t bh[2][2], bl[2][2];
                LDSM_X4(bh[0][0], bh[0][1], bh[1][0], bh[1][1], ka);
                LDSM_X4(bl[0][0], bl[0][1], bl[1][0], bl[1][1], ka + KV_ARR_H * 2);
#pragma unroll
                for (int j = 0; j < 2; j++) {
                    const int nf = 2 * nfp + j;
                    mma_f16(sc[nf], qfh[kc], bh[j]);
                    mma_f16(sc[nf], qfh[kc], bl[j]);
                    mma_f16(sc[nf], qfl[kc], bh[j]);
                }
            }
        }

        // ---- causal mask (last 4 tiles of this q-block) ----
        if (kt >= 4 * qt) {
            const int diag = (kt - 4 * qt) * 32;
            const int r0 = wid * 16 + g - diag;
            const int r1 = r0 + 8;
#pragma unroll
            for (int nf = 0; nf < 4; nf++) {
                const int c0 = nf * 8 + 2 * t;
                if (c0     > r0) sc[nf][0] = -1e30f;
                if (c0 + 1 > r0) sc[nf][1] = -1e30f;
                if (c0     > r1) sc[nf][2] = -1e30f;
                if (c0 + 1 > r1) sc[nf][3] = -1e30f;
            }
        }

        // ---- online softmax (deferred cross-thread l-sum) ----
        {
            float rm0 = -1e30f, rm1 = -1e30f;
#pragma unroll
            for (int nf = 0; nf < 4; nf++) {
                rm0 = fmaxf(rm0, fmaxf(sc[nf][0], sc[nf][1]));
                rm1 = fmaxf(rm1, fmaxf(sc[nf][2], sc[nf][3]));
            }
            rm0 = fmaxf(rm0, __shfl_xor_sync(0xffffffffu, rm0, 1));
            rm0 = fmaxf(rm0, __shfl_xor_sync(0xffffffffu, rm0, 2));
            rm1 = fmaxf(rm1, __shfl_xor_sync(0xffffffffu, rm1, 1));
            rm1 = fmaxf(rm1, __shfl_xor_sync(0xffffffffu, rm1, 2));

            const float mn0 = fmaxf(m0, rm0), mn1 = fmaxf(m1, rm1);
            const float cr0 = __expf(m0 - mn0), cr1 = __expf(m1 - mn1);
            float rs0 = 0.f, rs1 = 0.f;
#pragma unroll
            for (int nf = 0; nf < 4; nf++) {
                sc[nf][0] = __expf(sc[nf][0] - mn0);
                sc[nf][1] = __expf(sc[nf][1] - mn0);
                sc[nf][2] = __expf(sc[nf][2] - mn1);
                sc[nf][3] = __expf(sc[nf][3] - mn1);
                rs0 += sc[nf][0] + sc[nf][1];
                rs1 += sc[nf][2] + sc[nf][3];
            }
            l0 = l0 * cr0 + rs0;
            l1 = l1 * cr1 + rs1;
            m0 = mn0; m1 = mn1;
#pragma unroll
            for (int nf = 0; nf < 8; nf++) {
                oc[nf][0] *= cr0; oc[nf][1] *= cr0;
                oc[nf][2] *= cr1; oc[nf][3] *= cr1;
            }
        }

        // ---- O += P Vh, V frags via X4T pairs ----
#pragma unroll
        for (int kc = 0; kc < 2; kc++) {
            uint32_t pah[4];
            {
                const float* e0 = sc[2 * kc];
                const float* e1 = sc[2 * kc + 1];
                pah[0] = packh2(e0[0], e0[1]);
                pah[1] = packh2(e0[2], e0[3]);
                pah[2] = packh2(e1[0], e1[1]);
                pah[3] = packh2(e1[2], e1[3]);
            }
#pragma unroll
            for (int nfp = 0; nfp < 4; nfp++) {
                uint32_t vh[2][2];
                LDSM_X4T(vh[0][0], vh[0][1], vh[1][0], vh[1][1],
                         vO4 + stg + (uint32_t)(kc * (16 * APAD * 2) + nfp * 32));
                mma_f16(oc[2 * nfp],     pah, vh[0]);
                mma_f16(oc[2 * nfp + 1], pah, vh[1]);
            }
        }

        if (++buf == 3) buf = 0;
    }

    // ---- epilogue: finish l reduction, normalize, fp16 scatter ----
    l0 += __shfl_xor_sync(0xffffffffu, l0, 1);
    l0 += __shfl_xor_sync(0xffffffffu, l0, 2);
    l1 += __shfl_xor_sync(0xffffffffu, l1, 1);
    l1 += __shfl_xor_sync(0xffffffffu, l1, 2);
    const float inv0 = 1.0f / l0, inv1 = 1.0f / l1;
    const int n = nh >> 4;
    const int h = nh & 15;
    const int r0 = qb + wid * 16 + g;
    const int r1 = r0 + 8;
#pragma unroll
    for (int nf = 0; nf < 8; nf++) {
        const int col = h * HDIM + nf * 8 + 2 * t;
        *(uint32_t*)(Oh + (size_t)(n * LSEQ + r0) * EMBD + col) =
            packh2(oc[nf][0] * inv0, oc[nf][1] * inv0);
        *(uint32_t*)(Oh + (size_t)(n * LSEQ + r1) * EMBD + col) =
            packh2(oc[nf][2] * inv1, oc[nf][3] * inv1);
    }
}

// ------------------------- launch -------------------------
extern "C" void kernel_launch(void* const* d_in, const int* in_sizes, int n_in,
                              void* d_out, int out_size)
{
    (void)in_sizes; (void)n_in; (void)out_size;
    const float* x  = (const float*)d_in[0];
    const float* Wq = (const float*)d_in[2];
    const float* Wk = (const float*)d_in[3];
    const float* Wv = (const float*)d_in[4];
    const float* gq = (const float*)d_in[5];
    const float* bq = (const float*)d_in[6];
    const float* gk = (const float*)d_in[7];
    const float* bk = (const float*)d_in[8];
    const float* Wo = (const float*)d_in[9];
    const float* bo = (const float*)d_in[10];
    float* out = (float*)d_out;

    __half *xh, *xl, *wqh, *wql, *wkh, *wkl, *wvh, *woh;
    __half *qh, *ql, *kh, *kl, *vh, *oh;
    cudaGetSymbolAddress((void**)&xh, g_xh);   cudaGetSymbolAddress((void**)&xl, g_xl);
    cudaGetSymbolAddress((void**)&wqh, g_wqh); cudaGetSymbolAddress((void**)&wql, g_wql);
    cudaGetSymbolAddress((void**)&wkh, g_wkh); cudaGetSymbolAddress((void**)&wkl, g_wkl);
    cudaGetSymbolAddress((void**)&wvh, g_wvh);
    cudaGetSymbolAddress((void**)&woh, g_woh);
    cudaGetSymbolAddress((void**)&qh, g_qh);   cudaGetSymbolAddress((void**)&ql, g_ql);
    cudaGetSymbolAddress((void**)&kh, g_kh);   cudaGetSymbolAddress((void**)&kl, g_kl);
    cudaGetSymbolAddress((void**)&vh, g_vh);
    cudaGetSymbolAddress((void**)&oh, g_oh);

    cudaFuncSetAttribute(h16_gemm<0,3>, cudaFuncAttributeMaxDynamicSharedMemorySize, GEMM_SMEM);
    cudaFuncSetAttribute(h16_gemm<1,1>, cudaFuncAttributeMaxDynamicSharedMemorySize, GEMM_SMEM);
    cudaFuncSetAttribute(h16_gemm<2,1>, cudaFuncAttributeMaxDynamicSharedMemorySize, GEMM_SMEM);
    cudaFuncSetAttribute(attn_mma, cudaFuncAttributeMaxDynamicSharedMemorySize, ATTN_SMEM);

    // #1: fused split
    split_all<<<dim3(WN4 / 256, 5), 256>>>(
        (const float4*)x,  (uint2*)xh,  (uint2*)xl,
        (const float4*)Wq, (uint2*)wqh, (uint2*)wql,
        (const float4*)Wk, (uint2*)wkh, (uint2*)wkl,
        (const float4*)Wv, (uint2*)wvh,
        (const float4*)Wo, (uint2*)woh);

    dim3 gg(MROWS / 128, EMBD / 128);
    // #2: V first (attn stays launch #5 for ncu)
    h16_gemm<1,1><<<gg, 256, GEMM_SMEM>>>(xh, nullptr, wvh, nullptr, nullptr, nullptr, nullptr,
                                          vh, nullptr, nullptr);
    // #3, #4: Q, K projections
    h16_gemm<0,3><<<gg, 256, GEMM_SMEM>>>(xh, xl, wqh, wql, gq, bq, nullptr, qh, ql, nullptr);
    h16_gemm<0,3><<<gg, 256, GEMM_SMEM>>>(xh, xl, wkh, wkl, gk, bk, nullptr, kh, kl, nullptr);

    // #5: attention (128-q tiles, 8 warps)
    attn_mma<<<dim3(LSEQ / QROWS, NBATCH * NHEAD), 256, ATTN_SMEM>>>(qh, ql, kh, kl, vh, oh);

    // #6: output projection
    h16_gemm<2,1><<<gg, 256, GEMM_SMEM>>>(oh, nullptr, woh, nullptr, nullptr, nullptr, bo,
                                          nullptr, nullptr, out);
}